// round 1
// baseline (speedup 1.0000x reference)
#include <cuda_runtime.h>

#define FULLMASK 0xffffffffu

// Per-warp scratch layout (floats):
//   sh[64], sc[64], scr[64], sp[16], sA[16*17], sq[64*17]  -> 1568 floats
#define WS_FLOATS 1568

// One geodesic-ODE RHS evaluation for one point held by one warp.
// Lane l holds z_l (l<16: x component, l>=16: v component). Returns k_l.
__device__ __forceinline__ float warp_f(
    float zt, int lane,
    const float* __restrict__ sW1, const float* __restrict__ sW1T,
    const float* __restrict__ sW2, const float* __restrict__ sb1,
    const float* __restrict__ sb2, float* ws)
{
    float* sh  = ws;          // 64
    float* sc  = ws + 64;     // 64
    float* scr = ws + 128;    // 64
    float* sp  = ws + 192;    // 16
    float* sA  = ws + 208;    // 16*17 = 272
    float* sq  = ws + 480;    // 64*17 = 1088

    // ---- h = tanh(x W1 + b1), c = 1 - h^2 ; lane handles j = lane, lane+32 ----
    float pre0 = sb1[lane];
    float pre1 = sb1[lane + 32];
    #pragma unroll
    for (int i = 0; i < 16; ++i) {
        float xi = __shfl_sync(FULLMASK, zt, i);
        pre0 = fmaf(xi, sW1[i * 64 + lane],      pre0);
        pre1 = fmaf(xi, sW1[i * 64 + lane + 32], pre1);
    }
    float h0 = tanhf(pre0), h1 = tanhf(pre1);
    sh[lane]      = h0;  sh[lane + 32] = h1;
    sc[lane]      = 1.f - h0 * h0;
    sc[lane + 32] = 1.f - h1 * h1;

    // v components for this lane's owned columns: col(t) = lane + 32t,
    // a(t) = col/16 = (lane>>4) + 2t, b = lane & 15
    float va[8];
    #pragma unroll
    for (int t = 0; t < 8; ++t)
        va[t] = __shfl_sync(FULLMASK, zt, 16 + (lane >> 4) + 2 * t);

    __syncwarp();

    // ---- single pass over W2: A[col] += h_j * W2[j,col], q[j,b] += v_a * W2[j,col] ----
    float aA[8];
    #pragma unroll
    for (int t = 0; t < 8; ++t) aA[t] = sb2[lane + 32 * t];

    #pragma unroll 4
    for (int j = 0; j < 64; ++j) {
        float hj = sh[j];
        const float* w2r = sW2 + j * 256 + lane;
        float qp = 0.f;
        #pragma unroll
        for (int t = 0; t < 8; ++t) {
            float w = w2r[32 * t];
            aA[t] = fmaf(hj,    w, aA[t]);
            qp    = fmaf(va[t], w, qp);
        }
        qp += __shfl_xor_sync(FULLMASK, qp, 16);   // combine even/odd 'a' halves
        if (lane < 16) sq[j * 17 + lane] = qp;     // q[j, b=lane]
    }

    // ---- p_b = sum_a v_a A[a,b] ----
    float pp = 0.f;
    #pragma unroll
    for (int t = 0; t < 8; ++t) pp = fmaf(va[t], aA[t], pp);
    pp += __shfl_xor_sync(FULLMASK, pp, 16);
    if (lane < 16) sp[lane] = pp;

    // store A (row a, col b) with 17-padding
    #pragma unroll
    for (int t = 0; t < 8; ++t)
        sA[(2 * t + (lane >> 4)) * 17 + (lane & 15)] = aA[t];

    __syncwarp();

    // ---- r_j = q_j . p ;  scr[j] = c_j * r_j ; lane handles j = lane, lane+32 ----
    float r0 = 0.f, r1 = 0.f;
    #pragma unroll
    for (int b = 0; b < 16; ++b) {
        float pb = sp[b];
        r0 = fmaf(sq[lane * 17 + b],        pb, r0);
        r1 = fmaf(sq[(lane + 32) * 17 + b], pb, r1);
    }
    scr[lane]      = sc[lane]      * r0;
    scr[lane + 32] = sc[lane + 32] * r1;

    // ---- g = A A^T + I ; lane (r = lane&15) computes cols [8*(lane>>4), +8) ----
    int rrow = lane & 15;
    int cg   = (lane >> 4) * 8;
    float Ar[16];
    #pragma unroll
    for (int c = 0; c < 16; ++c) Ar[c] = sA[rrow * 17 + c];
    float gp[8];
    #pragma unroll
    for (int t = 0; t < 8; ++t) {
        float acc = (cg + t == rrow) ? 1.f : 0.f;
        #pragma unroll
        for (int c = 0; c < 16; ++c)
            acc = fmaf(Ar[c], sA[(cg + t) * 17 + c], acc);
        gp[t] = acc;
    }

    __syncwarp();

    // ---- s_i = sum_j W1[i,j] * scr[j]  (parity-split over lanes, xor-combined) ----
    float ssum = 0.f;
    int irow = lane & 15;
    int jo   = lane >> 4;
    #pragma unroll
    for (int jj = 0; jj < 32; ++jj) {
        int j = 2 * jj + jo;
        ssum = fmaf(sW1T[j * 16 + irow], scr[j], ssum);
    }
    ssum += __shfl_xor_sync(FULLMASK, ssum, 16);
    // NOTE: factors 2 (in s) and 1/2 (in dv) cancel: solve g y = ssum, dv = -y.

    // ---- assemble full row of g on lanes < 16 ----
    float grow[16];
    float rhs = ssum;
    #pragma unroll
    for (int t = 0; t < 8; ++t) {
        grow[t]     = gp[t];
        grow[8 + t] = __shfl_down_sync(FULLMASK, gp[t], 16);
    }

    // ---- Gaussian elimination without pivoting (g SPD, pivots >= ~1) ----
    #pragma unroll
    for (int k = 0; k < 16; ++k) {
        float piv = __shfl_sync(FULLMASK, grow[k], k);
        float pr  = __shfl_sync(FULLMASK, rhs,     k);
        float fct = grow[k] / piv;
        bool act = (lane > k) && (lane < 16);
        #pragma unroll
        for (int j = k + 1; j < 16; ++j) {
            float pj = __shfl_sync(FULLMASK, grow[j], k);
            if (act) grow[j] = fmaf(-fct, pj, grow[j]);
        }
        if (act) rhs = fmaf(-fct, pr, rhs);
    }
    // back substitution
    float y = 0.f;
    #pragma unroll
    for (int k = 15; k >= 0; --k) {
        float dk = __shfl_sync(FULLMASK, grow[k], k);
        float rk = __shfl_sync(FULLMASK, rhs,     k);
        float yk = rk / dk;
        if (lane == k) y = yk;
        if (lane < k) rhs = fmaf(-grow[k], yk, rhs);
    }

    // k-vector: lane<16 gets v (= zt at lane+16); lane>=16 gets dv = -y (from lane-16)
    float val = (lane < 16) ? (-y) : zt;
    float kout = __shfl_xor_sync(FULLMASK, val, 16);
    __syncwarp();
    return kout;
}

extern __shared__ float smem_dyn[];

__global__ void __launch_bounds__(256, 1)
geo_kernel(const float* __restrict__ z_in,
           const float* __restrict__ t_ptr,
           const float* __restrict__ W1,
           const float* __restrict__ b1,
           const float* __restrict__ W2,
           const float* __restrict__ b2,
           const int*   __restrict__ ns_ptr,
           float* __restrict__ z_out,
           int B)
{
    float* sW1  = smem_dyn;           // 16x64  [i*64+j]
    float* sW1T = smem_dyn + 1024;    // 64x16  [j*16+i]
    float* sW2  = smem_dyn + 2048;    // 64x256 [j*256+col]
    float* sb1  = smem_dyn + 18432;   // 64
    float* sb2  = smem_dyn + 18496;   // 256
    float* wsbase = smem_dyn + 18752; // 8 warps * 1568

    int tid = threadIdx.x;
    for (int idx = tid; idx < 1024; idx += 256) {
        float w = W1[idx];
        sW1[idx] = w;
        sW1T[(idx & 63) * 16 + (idx >> 6)] = w;
    }
    for (int idx = tid; idx < 4096; idx += 256)
        ((float4*)sW2)[idx] = ((const float4*)W2)[idx];
    if (tid < 64) sb1[tid] = b1[tid];
    if (tid < 256) { if (tid < 256) sb2[tid] = b2[tid]; }
    __syncthreads();

    int warp = tid >> 5, lane = tid & 31;
    int pt = blockIdx.x * 8 + warp;
    if (pt >= B) return;
    float* ws = wsbase + warp * WS_FLOATS;

    int ns = ns_ptr[0];
    float dt = t_ptr[0] / (float)ns;

    float z = z_in[pt * 32 + lane];

    #pragma unroll 1
    for (int step = 0; step < ns; ++step) {
        float k = 0.f, acc = 0.f;
        #pragma unroll 1
        for (int s = 0; s < 4; ++s) {
            float alpha = (s == 0) ? 0.f : ((s == 3) ? 1.f : 0.5f);
            float zt = fmaf(alpha * dt, k, z);
            k = warp_f(zt, lane, sW1, sW1T, sW2, sb1, sb2, ws);
            acc += ((s == 1 || s == 2) ? 2.f : 1.f) * k;
        }
        z = fmaf(dt / 6.f, acc, z);
    }
    z_out[pt * 32 + lane] = z;
}

extern "C" void kernel_launch(void* const* d_in, const int* in_sizes, int n_in,
                              void* d_out, int out_size)
{
    const float* z  = (const float*)d_in[0];
    const float* t  = (const float*)d_in[1];
    const float* W1 = (const float*)d_in[2];
    const float* b1 = (const float*)d_in[3];
    const float* W2 = (const float*)d_in[4];
    const float* b2 = (const float*)d_in[5];
    const int*   ns = (const int*)d_in[6];
    float* out = (float*)d_out;

    int B = in_sizes[0] / 32;                 // 16384 points
    int smem_bytes = (18752 + 8 * WS_FLOATS) * sizeof(float);  // 125184 B

    cudaFuncSetAttribute(geo_kernel,
                         cudaFuncAttributeMaxDynamicSharedMemorySize, smem_bytes);

    int blocks = (B + 7) / 8;
    geo_kernel<<<blocks, 256, smem_bytes>>>(z, t, W1, b1, W2, b2, ns, out, B);
}

// round 2
// speedup vs baseline: 1.3578x; 1.3578x over previous
#include <cuda_runtime.h>

#define FULLMASK 0xffffffffu
#define P 3
#define NWARP 8
// Per-warp-per-point scratch (floats): sh[64], sc[64], scr[64], sp[16], sA[16*17], sq[64*17]
#define WS_FLOATS 1568

// Width-16 Gaussian elimination (no pivoting; g SPD with eigenvalues >= 1).
// Each 16-lane segment solves its own system held as grow[16]/rhs per lane (= row l16).
__device__ __forceinline__ float solve16(float grow[16], float rhs, int l16)
{
    #pragma unroll
    for (int k = 0; k < 16; ++k) {
        float piv = __shfl_sync(FULLMASK, grow[k], k, 16);
        float pr  = __shfl_sync(FULLMASK, rhs,     k, 16);
        float fct = grow[k] / piv;
        bool act = (l16 > k);
        #pragma unroll
        for (int j = k + 1; j < 16; ++j) {
            float pj = __shfl_sync(FULLMASK, grow[j], k, 16);
            if (act) grow[j] = fmaf(-fct, pj, grow[j]);
        }
        if (act) rhs = fmaf(-fct, pr, rhs);
    }
    float y = 0.f;
    #pragma unroll
    for (int k = 15; k >= 0; --k) {
        float dk = __shfl_sync(FULLMASK, grow[k], k, 16);
        float rk = __shfl_sync(FULLMASK, rhs,     k, 16);
        float yk = rk / dk;
        if (l16 == k) y = yk;
        if (l16 < k) rhs = fmaf(-grow[k], yk, rhs);
    }
    return y;
}

// Evaluate geodesic ODE RHS for P=3 points at once (one warp, point state in zt[p]).
__device__ __forceinline__ void warp_f3(
    const float zt[P], float kout[P], int lane,
    const float* __restrict__ sW1, const float* __restrict__ sW1T,
    const float* __restrict__ sW2, const float* __restrict__ sb1,
    const float* __restrict__ sb2, float* ws)
{
    float* sh[P]; float* sc[P]; float* scr[P]; float* sp[P]; float* sA[P]; float* sq[P];
    #pragma unroll
    for (int p = 0; p < P; ++p) {
        float* b = ws + p * WS_FLOATS;
        sh[p] = b; sc[p] = b + 64; scr[p] = b + 128;
        sp[p] = b + 192; sA[p] = b + 208; sq[p] = b + 480;
    }

    // ---- h = tanh(x W1 + b1), c = 1 - h^2 (lane handles j = lane, lane+32) ----
    #pragma unroll
    for (int p = 0; p < P; ++p) {
        float pre0 = sb1[lane], pre1 = sb1[lane + 32];
        #pragma unroll
        for (int i = 0; i < 16; ++i) {
            float xi = __shfl_sync(FULLMASK, zt[p], i);
            pre0 = fmaf(xi, sW1[i * 64 + lane],      pre0);
            pre1 = fmaf(xi, sW1[i * 64 + lane + 32], pre1);
        }
        float h0 = tanhf(pre0), h1 = tanhf(pre1);
        sh[p][lane]      = h0;  sh[p][lane + 32] = h1;
        sc[p][lane]      = 1.f - h0 * h0;
        sc[p][lane + 32] = 1.f - h1 * h1;
    }

    // v components for owned W2 columns: col(t) = lane + 32t, a = (lane>>4)+2t
    float va[P][8];
    #pragma unroll
    for (int p = 0; p < P; ++p)
        #pragma unroll
        for (int t = 0; t < 8; ++t)
            va[p][t] = __shfl_sync(FULLMASK, zt[p], 16 + (lane >> 4) + 2 * t);

    __syncwarp();

    // ---- fused single pass over W2 for all P points ----
    float aA[P][8];
    #pragma unroll
    for (int t = 0; t < 8; ++t) {
        float bv = sb2[lane + 32 * t];
        #pragma unroll
        for (int p = 0; p < P; ++p) aA[p][t] = bv;
    }

    #pragma unroll 2
    for (int j = 0; j < 64; ++j) {
        float hj[P];
        #pragma unroll
        for (int p = 0; p < P; ++p) hj[p] = sh[p][j];
        const float* w2r = sW2 + j * 256 + lane;
        float qp[P] = {0.f, 0.f, 0.f};
        #pragma unroll
        for (int t = 0; t < 8; ++t) {
            float wv = w2r[32 * t];
            #pragma unroll
            for (int p = 0; p < P; ++p) {
                aA[p][t] = fmaf(hj[p],    wv, aA[p][t]);
                qp[p]    = fmaf(va[p][t], wv, qp[p]);
            }
        }
        #pragma unroll
        for (int p = 0; p < P; ++p) {
            qp[p] += __shfl_xor_sync(FULLMASK, qp[p], 16);
            if (lane < 16) sq[p][j * 17 + lane] = qp[p];
        }
    }

    // ---- p_b = sum_a v_a A[a,b]; store A with pad-17 ----
    #pragma unroll
    for (int p = 0; p < P; ++p) {
        float pp = 0.f;
        #pragma unroll
        for (int t = 0; t < 8; ++t) pp = fmaf(va[p][t], aA[p][t], pp);
        pp += __shfl_xor_sync(FULLMASK, pp, 16);
        if (lane < 16) sp[p][lane] = pp;
        #pragma unroll
        for (int t = 0; t < 8; ++t)
            sA[p][(2 * t + (lane >> 4)) * 17 + (lane & 15)] = aA[p][t];
    }

    __syncwarp();

    // ---- scr[j] = c_j * (q_j . p) ----
    #pragma unroll
    for (int p = 0; p < P; ++p) {
        float r0 = 0.f, r1 = 0.f;
        #pragma unroll
        for (int b = 0; b < 16; ++b) {
            float pb = sp[p][b];
            r0 = fmaf(sq[p][lane * 17 + b],        pb, r0);
            r1 = fmaf(sq[p][(lane + 32) * 17 + b], pb, r1);
        }
        scr[p][lane]      = sc[p][lane]      * r0;
        scr[p][lane + 32] = sc[p][lane + 32] * r1;
    }

    // ---- g = A A^T + I ; lane (row = lane&15) computes cols [8*(lane>>4), +8) ----
    int rrow = lane & 15;
    int cg   = (lane >> 4) * 8;
    float gp[P][8];
    #pragma unroll
    for (int p = 0; p < P; ++p) {
        float Ar[16];
        #pragma unroll
        for (int c = 0; c < 16; ++c) Ar[c] = sA[p][rrow * 17 + c];
        #pragma unroll
        for (int t = 0; t < 8; ++t) {
            float acc = (cg + t == rrow) ? 1.f : 0.f;
            #pragma unroll
            for (int c = 0; c < 16; ++c)
                acc = fmaf(Ar[c], sA[p][(cg + t) * 17 + c], acc);
            gp[p][t] = acc;
        }
    }

    __syncwarp();

    // ---- s_i = sum_j W1[i,j] * scr[j] (parity split, xor-16 combine) ----
    float ssum[P];
    int irow = lane & 15, jo = lane >> 4;
    #pragma unroll
    for (int p = 0; p < P; ++p) {
        float s = 0.f;
        #pragma unroll 8
        for (int jj = 0; jj < 32; ++jj) {
            int j = 2 * jj + jo;
            s = fmaf(sW1T[j * 16 + irow], scr[p][j], s);
        }
        s += __shfl_xor_sync(FULLMASK, s, 16);
        ssum[p] = s;
    }
    // (factor 2 in s and 1/2 in Gamma cancel: solve g y = s, dv = -y)

    bool lo = lane < 16;
    int  l16 = lane & 15;
    float grow[16], rhs;

    // pair solve: point 0 in lanes 0-15, point 1 in lanes 16-31
    #pragma unroll
    for (int t = 0; t < 8; ++t) {
        float a0 = __shfl_xor_sync(FULLMASK, gp[0][t], 16);
        float a1 = __shfl_xor_sync(FULLMASK, gp[1][t], 16);
        grow[t]     = lo ? gp[0][t] : a1;
        grow[8 + t] = lo ? a0       : gp[1][t];
    }
    rhs = lo ? ssum[0] : ssum[1];
    float ypair = solve16(grow, rhs, l16);

    // point 2: replicate system in both halves
    #pragma unroll
    for (int t = 0; t < 8; ++t) {
        float a2 = __shfl_xor_sync(FULLMASK, gp[2][t], 16);
        grow[t]     = lo ? gp[2][t] : a2;
        grow[8 + t] = lo ? a2       : gp[2][t];
    }
    rhs = ssum[2];
    float y2 = solve16(grow, rhs, l16);

    // ---- assemble k vectors: lane<16 -> v part, lane>=16 -> dv = -y ----
    float t0 = __shfl_xor_sync(FULLMASK, lo ? -ypair : zt[0], 16);
    kout[0] = t0;
    float t1s = __shfl_xor_sync(FULLMASK, zt[1], 16);
    kout[1] = lo ? t1s : -ypair;
    float t2 = __shfl_xor_sync(FULLMASK, lo ? -y2 : zt[2], 16);
    kout[2] = t2;
    __syncwarp();
}

extern __shared__ float smem_dyn[];

__global__ void __launch_bounds__(256, 1)
geo_kernel(const float* __restrict__ z_in,
           const float* __restrict__ t_ptr,
           const float* __restrict__ W1,
           const float* __restrict__ b1,
           const float* __restrict__ W2,
           const float* __restrict__ b2,
           const int*   __restrict__ ns_ptr,
           float* __restrict__ z_out,
           int B)
{
    float* sW1  = smem_dyn;           // 16x64  [i*64+j]
    float* sW1T = smem_dyn + 1024;    // 64x16  [j*16+i]
    float* sW2  = smem_dyn + 2048;    // 64x256 [j*256+col]
    float* sb1  = smem_dyn + 18432;   // 64
    float* sb2  = smem_dyn + 18496;   // 256
    float* wsbase = smem_dyn + 18752; // NWARP * P * WS_FLOATS

    int tid = threadIdx.x;
    for (int idx = tid; idx < 1024; idx += 256) {
        float w = W1[idx];
        sW1[idx] = w;
        sW1T[(idx & 63) * 16 + (idx >> 6)] = w;
    }
    for (int idx = tid; idx < 4096; idx += 256)
        ((float4*)sW2)[idx] = ((const float4*)W2)[idx];
    if (tid < 64) sb1[tid] = b1[tid];
    if (tid < 256) sb2[tid] = b2[tid];
    __syncthreads();

    int warp = tid >> 5, lane = tid & 31;
    float* ws = wsbase + warp * (P * WS_FLOATS);

    int pt0 = (blockIdx.x * NWARP + warp) * P;
    float z[P];
    #pragma unroll
    for (int p = 0; p < P; ++p) {
        int pt = pt0 + p;
        z[p] = (pt < B) ? z_in[pt * 32 + lane] : 0.f;
    }

    int ns = ns_ptr[0];
    float dt = t_ptr[0] / (float)ns;

    float kk[P], acc[P], zt[P];
    #pragma unroll 1
    for (int step = 0; step < ns; ++step) {
        #pragma unroll
        for (int p = 0; p < P; ++p) { kk[p] = 0.f; acc[p] = 0.f; }
        #pragma unroll 1
        for (int s = 0; s < 4; ++s) {
            float alpha = (s == 0) ? 0.f : ((s == 3) ? 1.f : 0.5f);
            float wgt   = (s == 1 || s == 2) ? 2.f : 1.f;
            #pragma unroll
            for (int p = 0; p < P; ++p) zt[p] = fmaf(alpha * dt, kk[p], z[p]);
            warp_f3(zt, kk, lane, sW1, sW1T, sW2, sb1, sb2, ws);
            #pragma unroll
            for (int p = 0; p < P; ++p) acc[p] += wgt * kk[p];
        }
        #pragma unroll
        for (int p = 0; p < P; ++p) z[p] = fmaf(dt / 6.f, acc[p], z[p]);
    }

    #pragma unroll
    for (int p = 0; p < P; ++p) {
        int pt = pt0 + p;
        if (pt < B) z_out[pt * 32 + lane] = z[p];
    }
}

extern "C" void kernel_launch(void* const* d_in, const int* in_sizes, int n_in,
                              void* d_out, int out_size)
{
    const float* z  = (const float*)d_in[0];
    const float* t  = (const float*)d_in[1];
    const float* W1 = (const float*)d_in[2];
    const float* b1 = (const float*)d_in[3];
    const float* W2 = (const float*)d_in[4];
    const float* b2 = (const float*)d_in[5];
    const int*   ns = (const int*)d_in[6];
    float* out = (float*)d_out;

    int B = in_sizes[0] / 32;                 // 16384 points
    int smem_bytes = (18752 + NWARP * P * WS_FLOATS) * sizeof(float);  // 225536 B

    cudaFuncSetAttribute(geo_kernel,
                         cudaFuncAttributeMaxDynamicSharedMemorySize, smem_bytes);

    int pts_per_block = NWARP * P;
    int blocks = (B + pts_per_block - 1) / pts_per_block;
    geo_kernel<<<blocks, 256, smem_bytes>>>(z, t, W1, b1, W2, b2, ns, out, B);
}

// round 4
// speedup vs baseline: 1.5330x; 1.1291x over previous
#include <cuda_runtime.h>

#define FULLMASK 0xffffffffu
#define P 3
#define NWARP 8
// Per-warp-per-point scratch (floats): sh/scr[64] (aliased), sc[64], sp[16], sA[16*18], sq[64*18]
#define WS_FLOATS 1584

typedef unsigned long long u64;

__device__ __forceinline__ u64 pk2(float lo, float hi) {
    u64 r; asm("mov.b64 %0, {%1,%2};" : "=l"(r) : "f"(lo), "f"(hi)); return r;
}
__device__ __forceinline__ void unpk(u64 a, float& lo, float& hi) {
    asm("mov.b64 {%0,%1}, %2;" : "=f"(lo), "=f"(hi) : "l"(a));
}
__device__ __forceinline__ u64 ffma2(u64 a, u64 b, u64 c) {
    u64 d; asm("fma.rn.f32x2 %0, %1, %2, %3;" : "=l"(d) : "l"(a), "l"(b), "l"(c)); return d;
}
__device__ __forceinline__ float tanh_fast(float x) {
    float y; asm("tanh.approx.f32 %0, %1;" : "=f"(y) : "f"(x)); return y;
}

// Dual width-16 Gaussian elimination (two independent SPD systems, interleaved chains).
__device__ __forceinline__ void solve16_dual(
    float ga[16], float ra, float gb[16], float rb, int l16, float& ya_o, float& yb_o)
{
    #pragma unroll
    for (int k = 0; k < 16; ++k) {
        float pva = __shfl_sync(FULLMASK, ga[k], k, 16);
        float pvb = __shfl_sync(FULLMASK, gb[k], k, 16);
        float pra = __shfl_sync(FULLMASK, ra,    k, 16);
        float prb = __shfl_sync(FULLMASK, rb,    k, 16);
        float fa = __fdividef(ga[k], pva);
        float fb = __fdividef(gb[k], pvb);
        bool act = (l16 > k);
        #pragma unroll
        for (int j = k + 1; j < 16; ++j) {
            float pja = __shfl_sync(FULLMASK, ga[j], k, 16);
            float pjb = __shfl_sync(FULLMASK, gb[j], k, 16);
            if (act) {
                ga[j] = fmaf(-fa, pja, ga[j]);
                gb[j] = fmaf(-fb, pjb, gb[j]);
            }
        }
        if (act) {
            ra = fmaf(-fa, pra, ra);
            rb = fmaf(-fb, prb, rb);
        }
    }
    float ya = 0.f, yb = 0.f;
    #pragma unroll
    for (int k = 15; k >= 0; --k) {
        float dka = __shfl_sync(FULLMASK, ga[k], k, 16);
        float dkb = __shfl_sync(FULLMASK, gb[k], k, 16);
        float rka = __shfl_sync(FULLMASK, ra,    k, 16);
        float rkb = __shfl_sync(FULLMASK, rb,    k, 16);
        float yka = __fdividef(rka, dka);
        float ykb = __fdividef(rkb, dkb);
        if (l16 == k) { ya = yka; yb = ykb; }
        if (l16 < k) {
            ra = fmaf(-ga[k], yka, ra);
            rb = fmaf(-gb[k], ykb, rb);
        }
    }
    ya_o = ya; yb_o = yb;
}

// Evaluate geodesic ODE RHS for P=3 points (one warp).
__device__ __forceinline__ void warp_f3(
    const float zt[P], float kout[P], int lane,
    const float* __restrict__ sW1p, const float* __restrict__ sW1Tp,
    const float* __restrict__ sW2x, const float* __restrict__ sb1,
    const float* __restrict__ sb2, float* ws)
{
    float* sh[P]; float* sc[P]; float* sp[P]; float* sA[P]; float* sq[P];
    #pragma unroll
    for (int p = 0; p < P; ++p) {
        float* b = ws + p * WS_FLOATS;
        sh[p] = b;            // 64 (aliased: scr overwrites after W2 pass)
        sc[p] = b + 64;       // 64
        sp[p] = b + 128;      // 16
        sA[p] = b + 144;      // 16*18
        sq[p] = b + 432;      // 64*18
    }

    // ---- h = tanh(x W1 + b1), c = 1 - h^2 ; lane owns j = lane, lane+32 ----
    const u64* w1p = (const u64*)sW1p;
    #pragma unroll
    for (int p = 0; p < P; ++p) {
        u64 pre2 = pk2(sb1[lane], sb1[lane + 32]);
        #pragma unroll
        for (int i = 0; i < 16; ++i) {
            float xi = __shfl_sync(FULLMASK, zt[p], i);
            pre2 = ffma2(pk2(xi, xi), w1p[i * 32 + lane], pre2);
        }
        float pr0, pr1; unpk(pre2, pr0, pr1);
        float h0 = tanh_fast(pr0), h1 = tanh_fast(pr1);
        sh[p][lane]      = h0;  sh[p][lane + 32] = h1;
        sc[p][lane]      = 1.f - h0 * h0;
        sc[p][lane + 32] = 1.f - h1 * h1;
    }

    // v pairs for owned W2 col-pairs: t2 covers cols (lane+64t2, lane+64t2+32)
    // a indices: a0 = (lane>>4)+4t2, a1 = a0+2
    u64 va2[P][4];
    #pragma unroll
    for (int p = 0; p < P; ++p)
        #pragma unroll
        for (int t2 = 0; t2 < 4; ++t2) {
            int a0 = (lane >> 4) + 4 * t2;
            float v0 = __shfl_sync(FULLMASK, zt[p], 16 + a0);
            float v1 = __shfl_sync(FULLMASK, zt[p], 16 + a0 + 2);
            va2[p][t2] = pk2(v0, v1);
        }

    __syncwarp();

    // ---- fused pass over W2: A accum + q rows (packed f32x2) ----
    u64 aA2[P][4];
    #pragma unroll
    for (int t2 = 0; t2 < 4; ++t2) {
        u64 bv = pk2(sb2[lane + 64 * t2], sb2[lane + 64 * t2 + 32]);
        #pragma unroll
        for (int p = 0; p < P; ++p) aA2[p][t2] = bv;
    }

    const u64* w2b = (const u64*)sW2x;
    #pragma unroll 2
    for (int j = 0; j < 64; ++j) {
        u64 h2[P];
        #pragma unroll
        for (int p = 0; p < P; ++p) { float hv = sh[p][j]; h2[p] = pk2(hv, hv); }
        const u64* w2r = w2b + j * 128 + lane;
        u64 q2[P] = {0ull, 0ull, 0ull};
        #pragma unroll
        for (int t2 = 0; t2 < 4; ++t2) {
            u64 w = w2r[t2 * 32];
            #pragma unroll
            for (int p = 0; p < P; ++p) {
                aA2[p][t2] = ffma2(h2[p],     w, aA2[p][t2]);
                q2[p]      = ffma2(va2[p][t2], w, q2[p]);
            }
        }
        #pragma unroll
        for (int p = 0; p < P; ++p) {
            float ql, qh; unpk(q2[p], ql, qh);
            float qp = ql + qh;
            qp += __shfl_xor_sync(FULLMASK, qp, 16);
            if (lane < 16) sq[p][j * 18 + lane] = qp;
        }
    }

    // ---- p_b = sum_a v_a A[a,b]; store A rows (pad 18) ----
    #pragma unroll
    for (int p = 0; p < P; ++p) {
        u64 pp2 = 0ull;
        #pragma unroll
        for (int t2 = 0; t2 < 4; ++t2) pp2 = ffma2(va2[p][t2], aA2[p][t2], pp2);
        float pl, ph; unpk(pp2, pl, ph);
        float pp = pl + ph;
        pp += __shfl_xor_sync(FULLMASK, pp, 16);
        if (lane < 16) sp[p][lane] = pp;
        int bcol = lane & 15;
        #pragma unroll
        for (int t2 = 0; t2 < 4; ++t2) {
            int a0 = (lane >> 4) + 4 * t2;
            float alo, ahi; unpk(aA2[p][t2], alo, ahi);
            sA[p][a0 * 18 + bcol]       = alo;
            sA[p][(a0 + 2) * 18 + bcol] = ahi;
        }
    }

    __syncwarp();

    // ---- scr[j] = c_j * (q_j . p)  (scr aliases sh) ----
    #pragma unroll
    for (int p = 0; p < P; ++p) {
        u64 r02 = 0ull, r12 = 0ull;
        #pragma unroll
        for (int b2 = 0; b2 < 8; ++b2) {
            u64 p2v = *(const u64*)&sp[p][2 * b2];
            u64 qa  = *(const u64*)&sq[p][lane * 18 + 2 * b2];
            u64 qb  = *(const u64*)&sq[p][(lane + 32) * 18 + 2 * b2];
            r02 = ffma2(qa, p2v, r02);
            r12 = ffma2(qb, p2v, r12);
        }
        float a, b2f, c, d;
        unpk(r02, a, b2f); unpk(r12, c, d);
        sh[p][lane]      = sc[p][lane]      * (a + b2f);   // scr
        sh[p][lane + 32] = sc[p][lane + 32] * (c + d);
    }

    // ---- g = A A^T + I (packed over c) ----
    int rrow = lane & 15;
    int cg   = (lane >> 4) * 8;
    float gp[P][8];
    #pragma unroll
    for (int p = 0; p < P; ++p) {
        u64 Ar2[8];
        #pragma unroll
        for (int c2 = 0; c2 < 8; ++c2)
            Ar2[c2] = *(const u64*)&sA[p][rrow * 18 + 2 * c2];
        #pragma unroll
        for (int t = 0; t < 8; ++t) {
            u64 acc2 = 0ull;
            #pragma unroll
            for (int c2 = 0; c2 < 8; ++c2) {
                u64 o = *(const u64*)&sA[p][(cg + t) * 18 + 2 * c2];
                acc2 = ffma2(Ar2[c2], o, acc2);
            }
            float al, ah; unpk(acc2, al, ah);
            gp[p][t] = al + ah + ((cg + t == rrow) ? 1.f : 0.f);
        }
    }

    __syncwarp();

    // ---- s_i = sum_j W1[i,j]*scr[j] (contiguous-half split + xor16 combine) ----
    float ssum[P];
    int irow = lane & 15, jo = lane >> 4;
    const u64* w1tp = (const u64*)sW1Tp;
    #pragma unroll
    for (int p = 0; p < P; ++p) {
        u64 s2 = 0ull;
        #pragma unroll
        for (int j2l = 0; j2l < 16; ++j2l) {
            int j2 = jo * 16 + j2l;
            u64 w = w1tp[j2 * 16 + irow];
            u64 cv = *(const u64*)&sh[p][2 * j2];   // scr
            s2 = ffma2(w, cv, s2);
        }
        float sl, shi; unpk(s2, sl, shi);
        float s = sl + shi;
        s += __shfl_xor_sync(FULLMASK, s, 16);
        ssum[p] = s;
    }
    // (factor 2 in s and 1/2 in Gamma cancel: solve g y = s, dv = -y)

    bool lo = lane < 16;
    int  l16 = lane & 15;

    // system A: pair (pt0 lanes 0-15, pt1 lanes 16-31); system B: pt2 replicated
    float ga[16], gb[16], ra, rb;
    #pragma unroll
    for (int t = 0; t < 8; ++t) {
        float a0 = __shfl_xor_sync(FULLMASK, gp[0][t], 16);
        float a1 = __shfl_xor_sync(FULLMASK, gp[1][t], 16);
        float a2 = __shfl_xor_sync(FULLMASK, gp[2][t], 16);
        ga[t]     = lo ? gp[0][t] : a1;
        ga[8 + t] = lo ? a0       : gp[1][t];
        gb[t]     = lo ? gp[2][t] : a2;
        gb[8 + t] = lo ? a2       : gp[2][t];
    }
    ra = lo ? ssum[0] : ssum[1];
    rb = ssum[2];

    float ypair, y2;
    solve16_dual(ga, ra, gb, rb, l16, ypair, y2);

    // ---- assemble k: lane<16 -> v part, lane>=16 -> dv = -y ----
    float t0 = __shfl_xor_sync(FULLMASK, lo ? -ypair : zt[0], 16);
    kout[0] = t0;
    float t1s = __shfl_xor_sync(FULLMASK, zt[1], 16);
    kout[1] = lo ? t1s : -ypair;
    float t2v = __shfl_xor_sync(FULLMASK, lo ? -y2 : zt[2], 16);
    kout[2] = t2v;
    __syncwarp();
}

extern __shared__ float smem_dyn[];

__global__ void __launch_bounds__(256, 1)
geo_kernel(const float* __restrict__ z_in,
           const float* __restrict__ t_ptr,
           const float* __restrict__ W1,
           const float* __restrict__ b1,
           const float* __restrict__ W2,
           const float* __restrict__ b2,
           const int*   __restrict__ ns_ptr,
           float* __restrict__ z_out,
           int B)
{
    float* sW1p  = smem_dyn;           // float2 pairs (W1[i,l], W1[i,l+32]) at f2-idx i*32+l
    float* sW1Tp = smem_dyn + 1024;    // float2 pairs (W1[i,2j2], W1[i,2j2+1]) at f2-idx j2*16+i
    float* sW2x  = smem_dyn + 2048;    // float2 pairs (W2[j,l+64t2], W2[j,l+64t2+32]) at f2-idx j*128+t2*32+l
    float* sb1   = smem_dyn + 18432;   // 64
    float* sb2   = smem_dyn + 18496;   // 256
    float* wsbase = smem_dyn + 18752;  // NWARP * P * WS_FLOATS

    int tid = threadIdx.x;
    for (int idx = tid; idx < 1024; idx += 256) {
        float w = W1[idx];
        int i = idx >> 6, j = idx & 63;
        sW1p [2 * (i * 32 + (j & 31)) + (j >> 5)] = w;
        sW1Tp[2 * ((j >> 1) * 16 + i) + (j & 1)]  = w;
    }
    for (int idx = tid; idx < 16384; idx += 256) {
        float w = W2[idx];
        int j = idx >> 8, c = idx & 255;
        int t = c >> 5, l = c & 31;
        sW2x[2 * (j * 128 + (t >> 1) * 32 + l) + (t & 1)] = w;
    }
    if (tid < 64) sb1[tid] = b1[tid];
    if (tid < 256) sb2[tid] = b2[tid];
    __syncthreads();

    int warp = tid >> 5, lane = tid & 31;
    float* ws = wsbase + warp * (P * WS_FLOATS);

    int pt0 = (blockIdx.x * NWARP + warp) * P;
    float z[P];
    #pragma unroll
    for (int p = 0; p < P; ++p) {
        int pt = pt0 + p;
        z[p] = (pt < B) ? z_in[pt * 32 + lane] : 0.f;
    }

    int ns = ns_ptr[0];
    float dt = t_ptr[0] / (float)ns;

    float kk[P], acc[P], zt[P];
    #pragma unroll 1
    for (int step = 0; step < ns; ++step) {
        #pragma unroll
        for (int p = 0; p < P; ++p) { kk[p] = 0.f; acc[p] = 0.f; }
        #pragma unroll 1
        for (int s = 0; s < 4; ++s) {
            float alpha = (s == 0) ? 0.f : ((s == 3) ? 1.f : 0.5f);
            float wgt   = (s == 1 || s == 2) ? 2.f : 1.f;
            #pragma unroll
            for (int p = 0; p < P; ++p) zt[p] = fmaf(alpha * dt, kk[p], z[p]);
            warp_f3(zt, kk, lane, sW1p, sW1Tp, sW2x, sb1, sb2, ws);
            #pragma unroll
            for (int p = 0; p < P; ++p) acc[p] += wgt * kk[p];
        }
        #pragma unroll
        for (int p = 0; p < P; ++p) z[p] = fmaf(dt / 6.f, acc[p], z[p]);
    }

    #pragma unroll
    for (int p = 0; p < P; ++p) {
        int pt = pt0 + p;
        if (pt < B) z_out[pt * 32 + lane] = z[p];
    }
}

extern "C" void kernel_launch(void* const* d_in, const int* in_sizes, int n_in,
                              void* d_out, int out_size)
{
    const float* z  = (const float*)d_in[0];
    const float* t  = (const float*)d_in[1];
    const float* W1 = (const float*)d_in[2];
    const float* b1 = (const float*)d_in[3];
    const float* W2 = (const float*)d_in[4];
    const float* b2 = (const float*)d_in[5];
    const int*   ns = (const int*)d_in[6];
    float* out = (float*)d_out;

    int B = in_sizes[0] / 32;                 // 16384 points
    int smem_bytes = (18752 + NWARP * P * WS_FLOATS) * sizeof(float);  // 227072 B

    cudaFuncSetAttribute(geo_kernel,
                         cudaFuncAttributeMaxDynamicSharedMemorySize, smem_bytes);

    int pts_per_block = NWARP * P;
    int blocks = (B + pts_per_block - 1) / pts_per_block;
    geo_kernel<<<blocks, 256, smem_bytes>>>(z, t, W1, b1, W2, b2, ns, out, B);
}

// round 5
// speedup vs baseline: 1.6685x; 1.0884x over previous
#include <cuda_runtime.h>

#define FULLMASK 0xffffffffu
#define P 4
#define NWARP 12
// Per-point scratch (floats): sh/scr[64] + sp[16] + sA/u[288]
#define WS_PT 368

typedef unsigned long long u64;

__device__ __forceinline__ u64 pk2(float lo, float hi) {
    u64 r; asm("mov.b64 %0, {%1,%2};" : "=l"(r) : "f"(lo), "f"(hi)); return r;
}
__device__ __forceinline__ void unpk(u64 a, float& lo, float& hi) {
    asm("mov.b64 {%0,%1}, %2;" : "=f"(lo), "=f"(hi) : "l"(a));
}
__device__ __forceinline__ u64 ffma2(u64 a, u64 b, u64 c) {
    u64 d; asm("fma.rn.f32x2 %0, %1, %2, %3;" : "=l"(d) : "l"(a), "l"(b), "l"(c)); return d;
}
__device__ __forceinline__ float tanh_fast(float x) {
    float y; asm("tanh.approx.f32 %0, %1;" : "=f"(y) : "f"(x)); return y;
}

// Dual width-16 Gaussian elimination (two independent SPD systems, interleaved).
__device__ __forceinline__ void solve16_dual(
    float ga[16], float ra, float gb[16], float rb, int l16, float& ya_o, float& yb_o)
{
    #pragma unroll
    for (int k = 0; k < 16; ++k) {
        float pva = __shfl_sync(FULLMASK, ga[k], k, 16);
        float pvb = __shfl_sync(FULLMASK, gb[k], k, 16);
        float pra = __shfl_sync(FULLMASK, ra,    k, 16);
        float prb = __shfl_sync(FULLMASK, rb,    k, 16);
        float fa = __fdividef(ga[k], pva);
        float fb = __fdividef(gb[k], pvb);
        bool act = (l16 > k);
        #pragma unroll
        for (int j = k + 1; j < 16; ++j) {
            float pja = __shfl_sync(FULLMASK, ga[j], k, 16);
            float pjb = __shfl_sync(FULLMASK, gb[j], k, 16);
            if (act) {
                ga[j] = fmaf(-fa, pja, ga[j]);
                gb[j] = fmaf(-fb, pjb, gb[j]);
            }
        }
        if (act) {
            ra = fmaf(-fa, pra, ra);
            rb = fmaf(-fb, prb, rb);
        }
    }
    float ya = 0.f, yb = 0.f;
    #pragma unroll
    for (int k = 15; k >= 0; --k) {
        float dka = __shfl_sync(FULLMASK, ga[k], k, 16);
        float dkb = __shfl_sync(FULLMASK, gb[k], k, 16);
        float rka = __shfl_sync(FULLMASK, ra,    k, 16);
        float rkb = __shfl_sync(FULLMASK, rb,    k, 16);
        float yka = __fdividef(rka, dka);
        float ykb = __fdividef(rkb, dkb);
        if (l16 == k) { ya = yka; yb = ykb; }
        if (l16 < k) {
            ra = fmaf(-ga[k], yka, ra);
            rb = fmaf(-gb[k], ykb, rb);
        }
    }
    ya_o = ya; yb_o = yb;
}

// Evaluate geodesic ODE RHS for P=4 points (one warp).
__device__ __forceinline__ void warp_f4(
    const float zt[P], float kout[P], int lane,
    const float* __restrict__ sW1p, const float* __restrict__ sW1Tp,
    const float* __restrict__ sW2x, const float* __restrict__ sW2r,
    const float* __restrict__ sb1, const float* __restrict__ sb2, float* ws)
{
    float* sh[P]; float* sp[P]; float* sA[P];
    #pragma unroll
    for (int p = 0; p < P; ++p) {
        float* b = ws + p * WS_PT;
        sh[p] = b;         // 64  (aliased: scr overwrites after m-pass)
        sp[p] = b + 64;    // 16
        sA[p] = b + 80;    // 16*18 = 288 (aliased: u[256] overwrites after g-pass)
    }

    // ---- h = tanh(x W1 + b1); c kept in registers (lane owns j=lane, lane+32) ----
    const u64* w1p = (const u64*)sW1p;
    float c0[P], c1[P];
    #pragma unroll
    for (int p = 0; p < P; ++p) {
        u64 pre2 = pk2(sb1[lane], sb1[lane + 32]);
        #pragma unroll
        for (int i = 0; i < 16; ++i) {
            float xi = __shfl_sync(FULLMASK, zt[p], i);
            pre2 = ffma2(pk2(xi, xi), w1p[i * 32 + lane], pre2);
        }
        float pr0, pr1; unpk(pre2, pr0, pr1);
        float h0 = tanh_fast(pr0), h1 = tanh_fast(pr1);
        sh[p][lane]      = h0;  sh[p][lane + 32] = h1;
        c0[p] = 1.f - h0 * h0;
        c1[p] = 1.f - h1 * h1;
    }

    // v pairs for owned W2 col-pairs: t2 covers cols (lane+64t2, lane+64t2+32)
    u64 va2[P][4];
    #pragma unroll
    for (int p = 0; p < P; ++p)
        #pragma unroll
        for (int t2 = 0; t2 < 4; ++t2) {
            int a0 = (lane >> 4) + 4 * t2;
            float v0 = __shfl_sync(FULLMASK, zt[p], 16 + a0);
            float v1 = __shfl_sync(FULLMASK, zt[p], 16 + a0 + 2);
            va2[p][t2] = pk2(v0, v1);
        }

    __syncwarp();

    // ---- W2 col-pass: A = h W2 + b2 (packed f32x2, no q) ----
    u64 aA2[P][4];
    #pragma unroll
    for (int t2 = 0; t2 < 4; ++t2) {
        u64 bv = pk2(sb2[lane + 64 * t2], sb2[lane + 64 * t2 + 32]);
        #pragma unroll
        for (int p = 0; p < P; ++p) aA2[p][t2] = bv;
    }
    const u64* w2b = (const u64*)sW2x;
    #pragma unroll 2
    for (int j = 0; j < 64; ++j) {
        u64 h2[P];
        #pragma unroll
        for (int p = 0; p < P; ++p) { float hv = sh[p][j]; h2[p] = pk2(hv, hv); }
        const u64* w2rp = w2b + j * 128 + lane;
        #pragma unroll
        for (int t2 = 0; t2 < 4; ++t2) {
            u64 w = w2rp[t2 * 32];
            #pragma unroll
            for (int p = 0; p < P; ++p) aA2[p][t2] = ffma2(h2[p], w, aA2[p][t2]);
        }
    }

    // ---- p_b = sum_a v_a A[a,b]; store p and A (pad 18) ----
    #pragma unroll
    for (int p = 0; p < P; ++p) {
        u64 pp2 = 0ull;
        #pragma unroll
        for (int t2 = 0; t2 < 4; ++t2) pp2 = ffma2(va2[p][t2], aA2[p][t2], pp2);
        float pl, ph; unpk(pp2, pl, ph);
        float pp = pl + ph;
        pp += __shfl_xor_sync(FULLMASK, pp, 16);
        if (lane < 16) sp[p][lane] = pp;
        int bcol = lane & 15;
        #pragma unroll
        for (int t2 = 0; t2 < 4; ++t2) {
            int a0 = (lane >> 4) + 4 * t2;
            float alo, ahi; unpk(aA2[p][t2], alo, ahi);
            sA[p][a0 * 18 + bcol]       = alo;
            sA[p][(a0 + 2) * 18 + bcol] = ahi;
        }
    }
    __syncwarp();

    // ---- g = A A^T + I ; lane (row = lane&15) computes cols [8*(lane>>4), +8) ----
    int rrow = lane & 15;
    int cg   = (lane >> 4) * 8;
    float gp[P][8];
    #pragma unroll
    for (int p = 0; p < P; ++p) {
        u64 Ar2[8];
        #pragma unroll
        for (int c2 = 0; c2 < 8; ++c2)
            Ar2[c2] = *(const u64*)&sA[p][rrow * 18 + 2 * c2];
        #pragma unroll
        for (int t = 0; t < 8; ++t) {
            u64 acc2 = 0ull;
            #pragma unroll
            for (int c2 = 0; c2 < 8; ++c2) {
                u64 o = *(const u64*)&sA[p][(cg + t) * 18 + 2 * c2];
                acc2 = ffma2(Ar2[c2], o, acc2);
            }
            float al, ah; unpk(acc2, al, ah);
            gp[p][t] = al + ah + ((cg + t == rrow) ? 1.f : 0.f);
        }
    }
    __syncwarp();   // all sA reads done before u overwrites

    // ---- build u = v (x) p in sA alias (256 floats, contiguous, 16B-aligned) ----
    #pragma unroll
    for (int p = 0; p < P; ++p) {
        float pb = sp[p][lane & 15];
        float* u = sA[p];
        #pragma unroll
        for (int t2 = 0; t2 < 4; ++t2) {
            float v0, v1; unpk(va2[p][t2], v0, v1);
            u[lane + 64 * t2]      = v0 * pb;
            u[lane + 64 * t2 + 32] = v1 * pb;
        }
    }
    __syncwarp();

    // ---- W2 row-pass: m_j = W2[j,:].u ; lane owns rows j=lane, lane+32 ----
    u64 mj0[P], mj1[P];
    #pragma unroll
    for (int p = 0; p < P; ++p) { mj0[p] = 0ull; mj1[p] = 0ull; }
    const float* r0p = sW2r + lane * 260;
    const float* r1p = sW2r + (lane + 32) * 260;
    #pragma unroll 8
    for (int k4 = 0; k4 < 64; ++k4) {
        float4 w0 = *(const float4*)(r0p + 4 * k4);
        float4 w1 = *(const float4*)(r1p + 4 * k4);
        u64 w0a = pk2(w0.x, w0.y), w0b = pk2(w0.z, w0.w);
        u64 w1a = pk2(w1.x, w1.y), w1b = pk2(w1.z, w1.w);
        #pragma unroll
        for (int p = 0; p < P; ++p) {
            float4 uu = *(const float4*)(sA[p] + 4 * k4);   // broadcast
            u64 ua = pk2(uu.x, uu.y), ub = pk2(uu.z, uu.w);
            mj0[p] = ffma2(ua, w0a, mj0[p]);
            mj0[p] = ffma2(ub, w0b, mj0[p]);
            mj1[p] = ffma2(ua, w1a, mj1[p]);
            mj1[p] = ffma2(ub, w1b, mj1[p]);
        }
    }
    // scr_j = c_j * m_j  (scr aliases sh)
    #pragma unroll
    for (int p = 0; p < P; ++p) {
        float a, b;
        unpk(mj0[p], a, b); sh[p][lane]      = c0[p] * (a + b);
        unpk(mj1[p], a, b); sh[p][lane + 32] = c1[p] * (a + b);
    }
    __syncwarp();

    // ---- s_i = sum_j W1[i,j]*scr[j] (contiguous-half split + xor16 combine) ----
    float ssum[P];
    int irow = lane & 15, jo = lane >> 4;
    const u64* w1tp = (const u64*)sW1Tp;
    #pragma unroll
    for (int p = 0; p < P; ++p) {
        u64 s2 = 0ull;
        #pragma unroll
        for (int j2l = 0; j2l < 16; ++j2l) {
            int j2 = jo * 16 + j2l;
            s2 = ffma2(w1tp[j2 * 16 + irow], *(const u64*)&sh[p][2 * j2], s2);
        }
        float sl, shi; unpk(s2, sl, shi);
        float s = sl + shi;
        s += __shfl_xor_sync(FULLMASK, s, 16);
        ssum[p] = s;
    }
    // (factor 2 in s and 1/2 in Gamma cancel: solve g y = s, dv = -y)

    bool lo = lane < 16;
    int  l16 = lane & 15;

    // sysA: pts 0/1 pair-packed; sysB: pts 2/3 pair-packed
    float ga[16], gb[16];
    #pragma unroll
    for (int t = 0; t < 8; ++t) {
        float a0 = __shfl_xor_sync(FULLMASK, gp[0][t], 16);
        float a1 = __shfl_xor_sync(FULLMASK, gp[1][t], 16);
        float a2 = __shfl_xor_sync(FULLMASK, gp[2][t], 16);
        float a3 = __shfl_xor_sync(FULLMASK, gp[3][t], 16);
        ga[t]     = lo ? gp[0][t] : a1;
        ga[8 + t] = lo ? a0       : gp[1][t];
        gb[t]     = lo ? gp[2][t] : a3;
        gb[8 + t] = lo ? a2       : gp[3][t];
    }
    float ra = lo ? ssum[0] : ssum[1];
    float rb = lo ? ssum[2] : ssum[3];

    float y01, y23;
    solve16_dual(ga, ra, gb, rb, l16, y01, y23);

    // ---- assemble k: lane<16 -> v part, lane>=16 -> dv = -y ----
    kout[0] = __shfl_xor_sync(FULLMASK, lo ? -y01 : zt[0], 16);
    float t1s = __shfl_xor_sync(FULLMASK, zt[1], 16);
    kout[1] = lo ? t1s : -y01;
    kout[2] = __shfl_xor_sync(FULLMASK, lo ? -y23 : zt[2], 16);
    float t3s = __shfl_xor_sync(FULLMASK, zt[3], 16);
    kout[3] = lo ? t3s : -y23;
    __syncwarp();
}

extern __shared__ float smem_dyn[];

__global__ void __launch_bounds__(NWARP * 32, 1)
geo_kernel(const float* __restrict__ z_in,
           const float* __restrict__ t_ptr,
           const float* __restrict__ W1,
           const float* __restrict__ b1,
           const float* __restrict__ W2,
           const float* __restrict__ b2,
           const int*   __restrict__ ns_ptr,
           float* __restrict__ z_out,
           int B)
{
    float* sW1p  = smem_dyn;           // u64 pairs (W1[i,l], W1[i,l+32]) at u64-idx i*32+l
    float* sW1Tp = smem_dyn + 1024;    // u64 pairs (W1[i,2j2], W1[i,2j2+1]) at u64-idx j2*16+i
    float* sW2x  = smem_dyn + 2048;    // u64 pairs (W2[j,l+64t2], W2[j,l+64t2+32]) at u64-idx j*128+t2*32+l
    float* sW2r  = smem_dyn + 18432;   // row-major, 260-fl padded rows: sW2r[j*260+c]
    float* sb1   = smem_dyn + 35072;   // 64
    float* sb2   = smem_dyn + 35136;   // 256
    float* wsbase = smem_dyn + 35392;  // NWARP * P * WS_PT

    int tid = threadIdx.x;
    const int NT = NWARP * 32;
    for (int idx = tid; idx < 1024; idx += NT) {
        float w = W1[idx];
        int i = idx >> 6, j = idx & 63;
        sW1p [2 * (i * 32 + (j & 31)) + (j >> 5)] = w;
        sW1Tp[2 * ((j >> 1) * 16 + i) + (j & 1)]  = w;
    }
    for (int idx = tid; idx < 16384; idx += NT) {
        float w = W2[idx];
        int j = idx >> 8, c = idx & 255;
        sW2r[j * 260 + c] = w;
        int tt = c >> 5, l = c & 31;
        sW2x[2 * (j * 128 + (tt >> 1) * 32 + l) + (tt & 1)] = w;
    }
    if (tid < 64) sb1[tid] = b1[tid];
    if (tid < 256) sb2[tid] = b2[tid];
    __syncthreads();

    int warp = tid >> 5, lane = tid & 31;
    float* ws = wsbase + warp * (P * WS_PT);

    int pt0 = (blockIdx.x * NWARP + warp) * P;
    float z[P];
    #pragma unroll
    for (int p = 0; p < P; ++p) {
        int pt = pt0 + p;
        z[p] = (pt < B) ? z_in[pt * 32 + lane] : 0.f;
    }

    int ns = ns_ptr[0];
    float dt = t_ptr[0] / (float)ns;

    float kk[P], acc[P], zt[P];
    #pragma unroll 1
    for (int step = 0; step < ns; ++step) {
        #pragma unroll
        for (int p = 0; p < P; ++p) { kk[p] = 0.f; acc[p] = 0.f; }
        #pragma unroll 1
        for (int s = 0; s < 4; ++s) {
            float alpha = (s == 0) ? 0.f : ((s == 3) ? 1.f : 0.5f);
            float wgt   = (s == 1 || s == 2) ? 2.f : 1.f;
            #pragma unroll
            for (int p = 0; p < P; ++p) zt[p] = fmaf(alpha * dt, kk[p], z[p]);
            warp_f4(zt, kk, lane, sW1p, sW1Tp, sW2x, sW2r, sb1, sb2, ws);
            #pragma unroll
            for (int p = 0; p < P; ++p) acc[p] += wgt * kk[p];
        }
        #pragma unroll
        for (int p = 0; p < P; ++p) z[p] = fmaf(dt / 6.f, acc[p], z[p]);
    }

    #pragma unroll
    for (int p = 0; p < P; ++p) {
        int pt = pt0 + p;
        if (pt < B) z_out[pt * 32 + lane] = z[p];
    }
}

extern "C" void kernel_launch(void* const* d_in, const int* in_sizes, int n_in,
                              void* d_out, int out_size)
{
    const float* z  = (const float*)d_in[0];
    const float* t  = (const float*)d_in[1];
    const float* W1 = (const float*)d_in[2];
    const float* b1 = (const float*)d_in[3];
    const float* W2 = (const float*)d_in[4];
    const float* b2 = (const float*)d_in[5];
    const int*   ns = (const int*)d_in[6];
    float* out = (float*)d_out;

    int B = in_sizes[0] / 32;                 // 16384 points
    int smem_bytes = (35392 + NWARP * P * WS_PT) * sizeof(float);  // 212,224 B

    cudaFuncSetAttribute(geo_kernel,
                         cudaFuncAttributeMaxDynamicSharedMemorySize, smem_bytes);

    int pts_per_block = NWARP * P;
    int blocks = (B + pts_per_block - 1) / pts_per_block;
    geo_kernel<<<blocks, NWARP * 32, smem_bytes>>>(z, t, W1, b1, W2, b2, ns, out, B);
}

// round 7
// speedup vs baseline: 2.2859x; 1.3700x over previous
#include <cuda_runtime.h>

#define FULLMASK 0xffffffffu
#define P 4
#define NWARP 14
// Per-point scratch (floats): sh/scr[64] + sp[16] + sA/u2[288]
#define WS_PT 368

typedef unsigned long long u64;

__device__ __forceinline__ u64 pk2(float lo, float hi) {
    u64 r; asm("mov.b64 %0, {%1,%2};" : "=l"(r) : "f"(lo), "f"(hi)); return r;
}
__device__ __forceinline__ void unpk(u64 a, float& lo, float& hi) {
    asm("mov.b64 {%0,%1}, %2;" : "=f"(lo), "=f"(hi) : "l"(a));
}
__device__ __forceinline__ u64 ffma2(u64 a, u64 b, u64 c) {
    u64 d; asm("fma.rn.f32x2 %0, %1, %2, %3;" : "=l"(d) : "l"(a), "l"(b), "l"(c)); return d;
}
__device__ __forceinline__ float tanh_fast(float x) {
    float y; asm("tanh.approx.f32 %0, %1;" : "=f"(y) : "f"(x)); return y;
}

// Dual width-16 Gaussian elimination (two independent SPD systems, interleaved).
__device__ __forceinline__ void solve16_dual(
    float ga[16], float ra, float gb[16], float rb, int l16, float& ya_o, float& yb_o)
{
    #pragma unroll
    for (int k = 0; k < 16; ++k) {
        float pva = __shfl_sync(FULLMASK, ga[k], k, 16);
        float pvb = __shfl_sync(FULLMASK, gb[k], k, 16);
        float pra = __shfl_sync(FULLMASK, ra,    k, 16);
        float prb = __shfl_sync(FULLMASK, rb,    k, 16);
        float fa = __fdividef(ga[k], pva);
        float fb = __fdividef(gb[k], pvb);
        bool act = (l16 > k);
        #pragma unroll
        for (int j = k + 1; j < 16; ++j) {
            float pja = __shfl_sync(FULLMASK, ga[j], k, 16);
            float pjb = __shfl_sync(FULLMASK, gb[j], k, 16);
            if (act) {
                ga[j] = fmaf(-fa, pja, ga[j]);
                gb[j] = fmaf(-fb, pjb, gb[j]);
            }
        }
        if (act) {
            ra = fmaf(-fa, pra, ra);
            rb = fmaf(-fb, prb, rb);
        }
    }
    float ya = 0.f, yb = 0.f;
    #pragma unroll
    for (int k = 15; k >= 0; --k) {
        float dka = __shfl_sync(FULLMASK, ga[k], k, 16);
        float dkb = __shfl_sync(FULLMASK, gb[k], k, 16);
        float rka = __shfl_sync(FULLMASK, ra,    k, 16);
        float rkb = __shfl_sync(FULLMASK, rb,    k, 16);
        float yka = __fdividef(rka, dka);
        float ykb = __fdividef(rkb, dkb);
        if (l16 == k) { ya = yka; yb = ykb; }
        if (l16 < k) {
            ra = fmaf(-ga[k], yka, ra);
            rb = fmaf(-gb[k], ykb, rb);
        }
    }
    ya_o = ya; yb_o = yb;
}

// Evaluate geodesic ODE RHS for P=4 points (one warp).
__device__ __forceinline__ void warp_f4(
    const float zt[P], float kout[P], int lane,
    const float* __restrict__ sW1p, const float* __restrict__ sW1Tp,
    const float* __restrict__ sW2u, const float* __restrict__ sb1,
    const float* __restrict__ sb2, float* ws)
{
    float* sh[P]; float* sp[P]; float* sA[P];
    #pragma unroll
    for (int p = 0; p < P; ++p) {
        float* b = ws + p * WS_PT;
        sh[p] = b;         // 64  (aliased: scr overwrites after row-pass)
        sp[p] = b + 64;    // 16
        sA[p] = b + 80;    // 16*18 = 288 (aliased: u2[130 u64] overwrites after g-pass)
    }

    // ---- h = tanh(x W1 + b1); c kept in registers (lane owns j=lane, lane+32) ----
    const u64* w1p = (const u64*)sW1p;
    float c0[P], c1[P];
    #pragma unroll
    for (int p = 0; p < P; ++p) {
        u64 pre2 = pk2(sb1[lane], sb1[lane + 32]);
        #pragma unroll
        for (int i = 0; i < 16; ++i) {
            float xi = __shfl_sync(FULLMASK, zt[p], i);
            pre2 = ffma2(pk2(xi, xi), w1p[i * 32 + lane], pre2);
        }
        float pr0, pr1; unpk(pre2, pr0, pr1);
        float h0 = tanh_fast(pr0), h1 = tanh_fast(pr1);
        sh[p][lane]      = h0;  sh[p][lane + 32] = h1;
        c0[p] = 1.f - h0 * h0;
        c1[p] = 1.f - h1 * h1;
    }
    __syncwarp();

    // ---- W2 col-pass: A = h W2 + b2 (pair layout, 130-u64 row stride) ----
    u64 aA2[P][4];
    #pragma unroll
    for (int t2 = 0; t2 < 4; ++t2) {
        u64 bv = pk2(sb2[lane + 64 * t2], sb2[lane + 64 * t2 + 32]);
        #pragma unroll
        for (int p = 0; p < P; ++p) aA2[p][t2] = bv;
    }
    const u64* w2u = (const u64*)sW2u;
    #pragma unroll 2
    for (int j = 0; j < 64; j += 4) {
        float4 hq[P];
        #pragma unroll
        for (int p = 0; p < P; ++p) hq[p] = *(const float4*)&sh[p][j];
        #pragma unroll
        for (int jj = 0; jj < 4; ++jj) {
            const u64* wrp = w2u + (j + jj) * 130 + lane;
            u64 w[4];
            #pragma unroll
            for (int t2 = 0; t2 < 4; ++t2) w[t2] = wrp[t2 * 32];
            #pragma unroll
            for (int p = 0; p < P; ++p) {
                float hv = (jj == 0) ? hq[p].x : (jj == 1) ? hq[p].y
                         : (jj == 2) ? hq[p].z : hq[p].w;
                u64 h2 = pk2(hv, hv);
                #pragma unroll
                for (int t2 = 0; t2 < 4; ++t2)
                    aA2[p][t2] = ffma2(h2, w[t2], aA2[p][t2]);
            }
        }
    }

    // ---- p_b = sum_a v_a A[a,b] (v re-shuffled from zt); store p and A ----
    #pragma unroll
    for (int p = 0; p < P; ++p) {
        u64 pp2 = 0ull;
        #pragma unroll
        for (int t2 = 0; t2 < 4; ++t2) {
            int a0 = (lane >> 4) + 4 * t2;
            float v0 = __shfl_sync(FULLMASK, zt[p], 16 + a0);
            float v1 = __shfl_sync(FULLMASK, zt[p], 16 + a0 + 2);
            pp2 = ffma2(pk2(v0, v1), aA2[p][t2], pp2);
        }
        float pl, ph; unpk(pp2, pl, ph);
        float pp = pl + ph;
        pp += __shfl_xor_sync(FULLMASK, pp, 16);
        if (lane < 16) sp[p][lane] = pp;
        int bcol = lane & 15;
        #pragma unroll
        for (int t2 = 0; t2 < 4; ++t2) {
            int a0 = (lane >> 4) + 4 * t2;
            float alo, ahi; unpk(aA2[p][t2], alo, ahi);
            sA[p][a0 * 18 + bcol]       = alo;
            sA[p][(a0 + 2) * 18 + bcol] = ahi;
        }
    }
    __syncwarp();

    // ---- g = A A^T + I ; lane (row = lane&15) computes cols [8*(lane>>4), +8) ----
    int rrow = lane & 15;
    int cg   = (lane >> 4) * 8;
    float gp[P][8];
    #pragma unroll
    for (int p = 0; p < P; ++p) {
        u64 Ar2[8];
        #pragma unroll
        for (int c2 = 0; c2 < 8; ++c2)
            Ar2[c2] = *(const u64*)&sA[p][rrow * 18 + 2 * c2];
        #pragma unroll
        for (int t = 0; t < 8; ++t) {
            u64 acc2 = 0ull;
            #pragma unroll
            for (int c2 = 0; c2 < 8; ++c2) {
                u64 o = *(const u64*)&sA[p][(cg + t) * 18 + 2 * c2];
                acc2 = ffma2(Ar2[c2], o, acc2);
            }
            float al, ah; unpk(acc2, al, ah);
            gp[p][t] = al + ah + ((cg + t == rrow) ? 1.f : 0.f);
        }
    }
    __syncwarp();   // all sA reads done before u2 overwrites

    // ---- build u2 (pair layout matching W2): u2[t2*32+lane] = (v0*pb, v1*pb) ----
    #pragma unroll
    for (int p = 0; p < P; ++p) {
        float pb = sp[p][lane & 15];
        u64* u2p = (u64*)sA[p];
        #pragma unroll
        for (int t2 = 0; t2 < 4; ++t2) {
            int a0 = (lane >> 4) + 4 * t2;
            float v0 = __shfl_sync(FULLMASK, zt[p], 16 + a0);
            float v1 = __shfl_sync(FULLMASK, zt[p], 16 + a0 + 2);
            u2p[t2 * 32 + lane] = pk2(v0 * pb, v1 * pb);
        }
    }
    __syncwarp();

    // ---- W2 row-pass: m_j = sum_m W2pair[j,m].u2[m] ; lane owns j=lane, lane+32 ----
    u64 mj0[P], mj1[P];
    #pragma unroll
    for (int p = 0; p < P; ++p) { mj0[p] = 0ull; mj1[p] = 0ull; }
    const u64* r0 = w2u + lane * 130;
    const u64* r1 = w2u + (lane + 32) * 130;
    #pragma unroll 8
    for (int m2 = 0; m2 < 64; ++m2) {
        float4 w0q = *(const float4*)(r0 + 2 * m2);
        float4 w1q = *(const float4*)(r1 + 2 * m2);
        u64 w0a = pk2(w0q.x, w0q.y), w0b = pk2(w0q.z, w0q.w);
        u64 w1a = pk2(w1q.x, w1q.y), w1b = pk2(w1q.z, w1q.w);
        #pragma unroll
        for (int p = 0; p < P; ++p) {
            float4 uu = *(const float4*)((const float*)sA[p] + 4 * m2);  // broadcast
            u64 ua = pk2(uu.x, uu.y), ub = pk2(uu.z, uu.w);
            mj0[p] = ffma2(ua, w0a, mj0[p]);
            mj0[p] = ffma2(ub, w0b, mj0[p]);
            mj1[p] = ffma2(ua, w1a, mj1[p]);
            mj1[p] = ffma2(ub, w1b, mj1[p]);
        }
    }
    // scr_j = c_j * m_j  (scr aliases sh)
    #pragma unroll
    for (int p = 0; p < P; ++p) {
        float a, b;
        unpk(mj0[p], a, b); sh[p][lane]      = c0[p] * (a + b);
        unpk(mj1[p], a, b); sh[p][lane + 32] = c1[p] * (a + b);
    }
    __syncwarp();

    // ---- s_i = sum_j W1[i,j]*scr[j] (contiguous-half split + xor16 combine) ----
    float ssum[P];
    int irow = lane & 15, jo = lane >> 4;
    const u64* w1tp = (const u64*)sW1Tp;
    #pragma unroll
    for (int p = 0; p < P; ++p) {
        u64 s2 = 0ull;
        #pragma unroll
        for (int j2l = 0; j2l < 16; ++j2l) {
            int j2 = jo * 16 + j2l;
            s2 = ffma2(w1tp[j2 * 16 + irow], *(const u64*)&sh[p][2 * j2], s2);
        }
        float sl, shi; unpk(s2, sl, shi);
        float s = sl + shi;
        s += __shfl_xor_sync(FULLMASK, s, 16);
        ssum[p] = s;
    }
    // (factor 2 in s and 1/2 in Gamma cancel: solve g y = s, dv = -y)

    bool lo = lane < 16;
    int  l16 = lane & 15;

    // sysA: pts 0/1 pair-packed; sysB: pts 2/3 pair-packed
    float ga[16], gb[16];
    #pragma unroll
    for (int t = 0; t < 8; ++t) {
        float a0 = __shfl_xor_sync(FULLMASK, gp[0][t], 16);
        float a1 = __shfl_xor_sync(FULLMASK, gp[1][t], 16);
        float a2 = __shfl_xor_sync(FULLMASK, gp[2][t], 16);
        float a3 = __shfl_xor_sync(FULLMASK, gp[3][t], 16);
        ga[t]     = lo ? gp[0][t] : a1;
        ga[8 + t] = lo ? a0       : gp[1][t];
        gb[t]     = lo ? gp[2][t] : a3;
        gb[8 + t] = lo ? a2       : gp[3][t];
    }
    float ra = lo ? ssum[0] : ssum[1];
    float rb = lo ? ssum[2] : ssum[3];

    float y01, y23;
    solve16_dual(ga, ra, gb, rb, l16, y01, y23);

    // ---- assemble k: lane<16 -> v part, lane>=16 -> dv = -y ----
    kout[0] = __shfl_xor_sync(FULLMASK, lo ? -y01 : zt[0], 16);
    float t1s = __shfl_xor_sync(FULLMASK, zt[1], 16);
    kout[1] = lo ? t1s : -y01;
    kout[2] = __shfl_xor_sync(FULLMASK, lo ? -y23 : zt[2], 16);
    float t3s = __shfl_xor_sync(FULLMASK, zt[3], 16);
    kout[3] = lo ? t3s : -y23;
    __syncwarp();
}

extern __shared__ float smem_dyn[];

__global__ void __launch_bounds__(NWARP * 32, 1)
geo_kernel(const float* __restrict__ z_in,
           const float* __restrict__ t_ptr,
           const float* __restrict__ W1,
           const float* __restrict__ b1,
           const float* __restrict__ W2,
           const float* __restrict__ b2,
           const int*   __restrict__ ns_ptr,
           float* __restrict__ z_out,
           int B)
{
    float* sW1p  = smem_dyn;           // u64 pairs (W1[i,l], W1[i,l+32]) at u64-idx i*32+l
    float* sW1Tp = smem_dyn + 1024;    // u64 pairs (W1[i,2j2], W1[i,2j2+1]) at u64-idx j2*16+i
    float* sW2u  = smem_dyn + 2048;    // u64 pairs (W2[j,l+64t2], W2[j,l+64t2+32]) at u64-idx j*130+t2*32+l
    float* sb1   = smem_dyn + 18688;   // 64
    float* sb2   = smem_dyn + 18752;   // 256
    float* wsbase = smem_dyn + 19008;  // NWARP * P * WS_PT

    int tid = threadIdx.x;
    const int NT = NWARP * 32;
    for (int idx = tid; idx < 1024; idx += NT) {
        float w = W1[idx];
        int i = idx >> 6, j = idx & 63;
        sW1p [2 * (i * 32 + (j & 31)) + (j >> 5)] = w;
        sW1Tp[2 * ((j >> 1) * 16 + i) + (j & 1)]  = w;
    }
    for (int idx = tid; idx < 16384; idx += NT) {
        float w = W2[idx];
        int j = idx >> 8, c = idx & 255;
        int tt = c >> 5, l = c & 31;
        sW2u[2 * (j * 130 + (tt >> 1) * 32 + l) + (tt & 1)] = w;
    }
    if (tid < 64) sb1[tid] = b1[tid];
    if (tid < 256) sb2[tid] = b2[tid];
    __syncthreads();

    int warp = tid >> 5, lane = tid & 31;
    float* ws = wsbase + warp * (P * WS_PT);

    int pt0 = (blockIdx.x * NWARP + warp) * P;
    float z[P];
    #pragma unroll
    for (int p = 0; p < P; ++p) {
        int pt = pt0 + p;
        z[p] = (pt < B) ? z_in[pt * 32 + lane] : 0.f;
    }

    int ns = ns_ptr[0];
    float dt = t_ptr[0] / (float)ns;

    float kk[P], acc[P], zt[P];
    #pragma unroll 1
    for (int step = 0; step < ns; ++step) {
        #pragma unroll
        for (int p = 0; p < P; ++p) { kk[p] = 0.f; acc[p] = 0.f; }
        #pragma unroll 1
        for (int s = 0; s < 4; ++s) {
            float alpha = (s == 0) ? 0.f : ((s == 3) ? 1.f : 0.5f);
            float wgt   = (s == 1 || s == 2) ? 2.f : 1.f;
            #pragma unroll
            for (int p = 0; p < P; ++p) zt[p] = fmaf(alpha * dt, kk[p], z[p]);
            warp_f4(zt, kk, lane, sW1p, sW1Tp, sW2u, sb1, sb2, ws);
            #pragma unroll
            for (int p = 0; p < P; ++p) acc[p] += wgt * kk[p];
        }
        #pragma unroll
        for (int p = 0; p < P; ++p) z[p] = fmaf(dt / 6.f, acc[p], z[p]);
    }

    #pragma unroll
    for (int p = 0; p < P; ++p) {
        int pt = pt0 + p;
        if (pt < B) z_out[pt * 32 + lane] = z[p];
    }
}

extern "C" void kernel_launch(void* const* d_in, const int* in_sizes, int n_in,
                              void* d_out, int out_size)
{
    const float* z  = (const float*)d_in[0];
    const float* t  = (const float*)d_in[1];
    const float* W1 = (const float*)d_in[2];
    const float* b1 = (const float*)d_in[3];
    const float* W2 = (const float*)d_in[4];
    const float* b2 = (const float*)d_in[5];
    const int*   ns = (const int*)d_in[6];
    float* out = (float*)d_out;

    int B = in_sizes[0] / 32;                 // 16384 points
    int smem_bytes = (19008 + NWARP * P * WS_PT) * sizeof(float);  // 158,464 B

    cudaFuncSetAttribute(geo_kernel,
                         cudaFuncAttributeMaxDynamicSharedMemorySize, smem_bytes);

    int pts_per_block = NWARP * P;
    int blocks = (B + pts_per_block - 1) / pts_per_block;
    geo_kernel<<<blocks, NWARP * 32, smem_bytes>>>(z, t, W1, b1, W2, b2, ns, out, B);
}